// round 8
// baseline (speedup 1.0000x reference)
#include <cuda_runtime.h>
#include <cuda_bf16.h>
#include <cstdint>

// Problem constants
#define B_   16
#define C_   256
#define HW_  1024
#define K_   8192
#define N_   16384            // tokens
#define NQE  4194304          // qe elems

// Tiling
#define TM 128                 // tokens per CTA
#define TN 128                 // codes per CTA
#define KCH 32                 // K chunk (floats) = 16 k-pairs
#define NCHUNK (C_ / KCH)      // 8
#define NCAND 256              // candidates per token (64 ctaY * 2 nwarps * 2)
#define MARGIN 0.25f

// smem (uint32 units). A: [kp][t] hi-only, stride 136 (8 mod 32 -> conflict-free)
// B: [nr][kp] uint2 (hi-pair, lo-pair), stride 18 uint2
#define AST_A 136
#define A_U32 (16 * AST_A)             // 2176
#define BST 18                          // uint2 stride
#define B_U32 (128 * BST * 2)           // 4608
#define STAGE_U32 (A_U32 + B_U32)       // 6784
#define SMEM_BYTES (2 * STAGE_U32 * 4)  // 54272

// Scratch
__device__ unsigned long long g_cand[(size_t)N_ * NCAND];   // 32MB
__device__ unsigned int g_idx[N_];
__device__ float g_cnorm[K_];
__device__ float g_partial[B_ * C_];

__device__ __forceinline__ unsigned int fkey(float f) {
    unsigned int b = __float_as_uint(f);
    return (b & 0x80000000u) ? ~b : (b | 0x80000000u);
}
__device__ __forceinline__ float unfkey(unsigned int k) {
    unsigned int b = (k & 0x80000000u) ? (k & 0x7FFFFFFFu) : ~k;
    return __uint_as_float(b);
}

__device__ __forceinline__ uint32_t hi_pair(float v0, float v1) {
    __nv_bfloat162 hp = __floats2bfloat162_rn(v0, v1);
    return *(uint32_t*)&hp;
}
// (hi-pair, lo-pair) for B
__device__ __forceinline__ uint2 split_pair(float v0, float v1) {
    __nv_bfloat16 h0 = __float2bfloat16_rn(v0);
    __nv_bfloat16 h1 = __float2bfloat16_rn(v1);
    float l0 = v0 - __bfloat162float(h0);
    float l1 = v1 - __bfloat162float(h1);
    __nv_bfloat162 hp; hp.x = h0; hp.y = h1;
    __nv_bfloat162 lp = __floats2bfloat162_rn(l0, l1);
    uint2 r;
    r.x = *(uint32_t*)&hp;
    r.y = *(uint32_t*)&lp;
    return r;
}

#define MMA_BF16(D, A, B0, B1)                                              \
    asm volatile("mma.sync.aligned.m16n8k16.row.col.f32.bf16.bf16.f32 "     \
        "{%0,%1,%2,%3},{%4,%5,%6,%7},{%8,%9},{%0,%1,%2,%3};"                \
        : "+f"((D)[0]), "+f"((D)[1]), "+f"((D)[2]), "+f"((D)[3])            \
        : "r"((A)[0]), "r"((A)[1]), "r"((A)[2]), "r"((A)[3]),               \
          "r"(B0), "r"(B1))

// ---------------------------------------------------------------------------
// Kernel 1: codebook squared norms
__global__ void cnorm_kernel(const float* __restrict__ cb) {
    int code = blockIdx.x * 8 + (threadIdx.x >> 5);
    int lane = threadIdx.x & 31;
    const float4* row = (const float4*)(cb + (size_t)code * C_);
    float s = 0.0f;
#pragma unroll
    for (int r = 0; r < 2; r++) {
        float4 v = row[lane + 32 * r];
        s += v.x * v.x + v.y * v.y + v.z * v.z + v.w * v.w;
    }
#pragma unroll
    for (int off = 16; off; off >>= 1)
        s += __shfl_xor_sync(0xFFFFFFFFu, s, off);
    if (lane == 0) g_cnorm[code] = s;
}

// ---------------------------------------------------------------------------
// Kernel 2: bf16 2-term screening GEMM (hi_x * (hi_e + lo_e) = hi_x * e),
// two-pass accumulator scheduling, top-2 candidates per n-warp per token.
// grid=(128,64), block=256 (4m x 2n warps).
__global__ void __launch_bounds__(256, 2)
argmin_mma_kernel(const float* __restrict__ x, const float* __restrict__ cb) {
    extern __shared__ uint32_t smemu[];
    __shared__ float cnS[TN];

    const int tid = threadIdx.x;
    const int wid = tid >> 5;
    const int lane = tid & 31;
    const int g  = lane >> 2;
    const int tg = lane & 3;
    const int m0w = (wid & 3) * 32;
    const int n0w = (wid >> 2) * 64;

    const int n0tok = blockIdx.x * TM;
    const int b   = n0tok >> 10;
    const int hw0 = n0tok & 1023;
    const int j0  = blockIdx.y * TN;

    if (tid < TN) cnS[tid] = g_cnorm[j0 + tid];

    const float* ga = x + (size_t)b * C_ * HW_ + hw0;   // [c][t] stride HW_
    const float* gb = cb + (size_t)j0 * C_;             // [n][c] row-major

    float d[2][8][4];
#pragma unroll
    for (int i = 0; i < 2; i++)
#pragma unroll
        for (int j = 0; j < 8; j++)
#pragma unroll
            for (int e = 0; e < 4; e++) d[i][j][e] = 0.0f;

    float2 va2[8];
    float4 vb[4];

    auto gld = [&](int k) {
        const int c0 = k * KCH;
#pragma unroll
        for (int r = 0; r < 8; r++) {
            int idx = tid + r * 256;
            int t = idx & 127, kp = idx >> 7;
            va2[r].x = ga[(size_t)(c0 + 2 * kp) * HW_ + t];
            va2[r].y = ga[(size_t)(c0 + 2 * kp + 1) * HW_ + t];
        }
#pragma unroll
        for (int s = 0; s < 4; s++) {
            int f4 = tid + s * 256;
            int rowB = f4 >> 3, q = f4 & 7;
            vb[s] = *(const float4*)(gb + (size_t)rowB * C_ + c0 + q * 4);
        }
    };

    auto sts = [&](int stg) {
        uint32_t* As = smemu + stg * STAGE_U32;
        uint2* Bs = (uint2*)(As + A_U32);
#pragma unroll
        for (int r = 0; r < 8; r++) {
            int idx = tid + r * 256;
            int t = idx & 127, kp = idx >> 7;
            As[kp * AST_A + t] = hi_pair(va2[r].x, va2[r].y);
        }
#pragma unroll
        for (int s = 0; s < 4; s++) {
            int f4 = tid + s * 256;
            int rowB = f4 >> 3, q = f4 & 7;
            Bs[rowB * BST + 2 * q]     = split_pair(vb[s].x, vb[s].y);
            Bs[rowB * BST + 2 * q + 1] = split_pair(vb[s].z, vb[s].w);
        }
    };

    auto mma_stage = [&](int stg) {
        const uint32_t* As = smemu + stg * STAGE_U32;
        const uint2* Bs = (const uint2*)(As + A_U32);
#pragma unroll
        for (int kk = 0; kk < 2; kk++) {
            const int kb = kk * 8 + tg;
            uint32_t ah[2][4];
#pragma unroll
            for (int dm = 0; dm < 2; dm++) {
                int mc = m0w + 16 * dm + g;
                ah[dm][0] = As[kb * AST_A + mc];
                ah[dm][1] = As[kb * AST_A + mc + 8];
                ah[dm][2] = As[(kb + 4) * AST_A + mc];
                ah[dm][3] = As[(kb + 4) * AST_A + mc + 8];
            }
            // pass 1: hi * hi over all 16 accumulators
#pragma unroll
            for (int dn = 0; dn < 8; dn++) {
                int nr = n0w + 8 * dn + g;
                uint2 q0 = Bs[nr * BST + kb];
                uint2 q1 = Bs[nr * BST + kb + 4];
                MMA_BF16(d[0][dn], ah[0], q0.x, q1.x);
                MMA_BF16(d[1][dn], ah[1], q0.x, q1.x);
            }
            // pass 2: hi * lo over all 16 accumulators (reuse gap = 15 MMAs)
#pragma unroll
            for (int dn = 0; dn < 8; dn++) {
                int nr = n0w + 8 * dn + g;
                uint2 q0 = Bs[nr * BST + kb];
                uint2 q1 = Bs[nr * BST + kb + 4];
                MMA_BF16(d[0][dn], ah[0], q0.y, q1.y);
                MMA_BF16(d[1][dn], ah[1], q0.y, q1.y);
            }
        }
    };

    gld(0);
    sts(0);
    __syncthreads();
#pragma unroll 1
    for (int k = 0; k < NCHUNK; k++) {
        if (k + 1 < NCHUNK) gld(k + 1);
        mma_stage(k & 1);
        if (k + 1 < NCHUNK) sts((k + 1) & 1);
        __syncthreads();
    }

    // epilogue: per n-warp top-2 per token row, race-free candidate writes
#pragma unroll
    for (int dm = 0; dm < 2; dm++) {
#pragma unroll
        for (int h = 0; h < 2; h++) {
            unsigned long long p1 = 0xFFFFFFFFFFFFFFFFull;
            unsigned long long p2 = 0xFFFFFFFFFFFFFFFFull;
#pragma unroll
            for (int dn = 0; dn < 8; dn++) {
#pragma unroll
                for (int e = 0; e < 2; e++) {
                    int col = n0w + 8 * dn + 2 * tg + e;
                    float sc = fmaf(-2.0f, d[dm][dn][2 * h + e], cnS[col]);
                    unsigned long long p =
                        ((unsigned long long)fkey(sc) << 32) |
                        (unsigned int)(j0 + col);
                    if (p < p1) { p2 = p1; p1 = p; }
                    else if (p < p2) { p2 = p; }
                }
            }
#pragma unroll
            for (int off = 1; off <= 2; off <<= 1) {
                unsigned long long q1 = __shfl_xor_sync(0xFFFFFFFFu, p1, off);
                unsigned long long q2 = __shfl_xor_sync(0xFFFFFFFFu, p2, off);
                if (q1 < p1) { p2 = (p1 < q2) ? p1 : q2; p1 = q1; }
                else         { p2 = (p2 < q1) ? p2 : q1; }
            }
            if (tg == 0) {
                int tok = n0tok + m0w + 16 * dm + 8 * h + g;
                size_t base = (size_t)tok * NCAND + blockIdx.y * 4 + (wid >> 2) * 2;
                g_cand[base] = p1;
                g_cand[base + 1] = p2;
            }
        }
    }
}

// ---------------------------------------------------------------------------
// Kernel 3: exact fp32 rerank. One warp per token over 256 candidates.
__global__ void __launch_bounds__(256)
rerank_kernel(const float* __restrict__ x, const float* __restrict__ cb) {
    const int wid = threadIdx.x >> 5;
    const int lane = threadIdx.x & 31;
    const int tok = blockIdx.x * 8 + wid;
    const unsigned long long* cand = g_cand + (size_t)tok * NCAND;

    unsigned long long v[8];
    unsigned long long mn = 0xFFFFFFFFFFFFFFFFull;
#pragma unroll
    for (int r = 0; r < 8; r++) {
        v[r] = cand[lane + 32 * r];
        if (v[r] < mn) mn = v[r];
    }
#pragma unroll
    for (int off = 16; off; off >>= 1) {
        unsigned long long o = __shfl_xor_sync(0xFFFFFFFFu, mn, off);
        if (o < mn) mn = o;
    }
    const float thr = unfkey((unsigned int)(mn >> 32)) + MARGIN;

    const int b = tok >> 10, hw = tok & 1023;
    const float* xt = x + (size_t)b * C_ * HW_ + hw;
    float xr[8];
#pragma unroll
    for (int q = 0; q < 8; q++)
        xr[q] = xt[(size_t)(lane + 32 * q) * HW_];

    float best_s = __uint_as_float(0x7F800000u);   // +inf
    unsigned int best_j = 0xFFFFFFFFu;
#pragma unroll 1
    for (int r = 0; r < 8; r++) {
        float sf = unfkey((unsigned int)(v[r] >> 32));
        unsigned int m = __ballot_sync(0xFFFFFFFFu, sf <= thr);
        while (m) {
            int src = __ffs(m) - 1;
            m &= m - 1;
            unsigned long long c = __shfl_sync(0xFFFFFFFFu, v[r], src);
            unsigned int j = (unsigned int)c;
            const float* row = cb + (size_t)j * C_;
            float dot = 0.0f;
#pragma unroll
            for (int q = 0; q < 8; q++)
                dot = fmaf(xr[q], row[lane + 32 * q], dot);
#pragma unroll
            for (int off = 16; off; off >>= 1)
                dot += __shfl_xor_sync(0xFFFFFFFFu, dot, off);
            float sc = fmaf(-2.0f, dot, g_cnorm[j]);
            if (sc < best_s || (sc == best_s && j < best_j)) {
                best_s = sc;
                best_j = j;
            }
        }
    }
    if (lane == 0) g_idx[tok] = best_j;
}

// ---------------------------------------------------------------------------
// Kernel 4: gather q, write qe + indices, per-block loss partials
__global__ void gather_kernel(const float* __restrict__ x,
                              const float* __restrict__ cb,
                              float* __restrict__ out) {
    const int bc = blockIdx.x;
    const int b = bc >> 8, c = bc & 255;
    const float* xrow = x + (size_t)bc * HW_;
    float* orow = out + (size_t)bc * HW_;
    float lsum = 0.0f;
#pragma unroll
    for (int r = 0; r < 4; r++) {
        int hw = threadIdx.x + r * 256;
        int n = b * HW_ + hw;
        unsigned int idx = g_idx[n];
        float q = cb[(size_t)idx * C_ + c];
        float dd = xrow[hw] - q;
        lsum += dd * dd;
        orow[hw] = q;
        if (c == 0) out[NQE + 1 + n] = (float)idx;
    }
    __shared__ float red[256];
    red[threadIdx.x] = lsum;
    __syncthreads();
#pragma unroll
    for (int s = 128; s; s >>= 1) {
        if (threadIdx.x < s) red[threadIdx.x] += red[threadIdx.x + s];
        __syncthreads();
    }
    if (threadIdx.x == 0) g_partial[bc] = red[0];
}

// Kernel 5: deterministic final loss reduction
__global__ void loss_kernel(float* __restrict__ out) {
    __shared__ float red[256];
    float s = 0.0f;
    for (int i = threadIdx.x; i < B_ * C_; i += 256) s += g_partial[i];
    red[threadIdx.x] = s;
    __syncthreads();
#pragma unroll
    for (int st = 128; st; st >>= 1) {
        if (threadIdx.x < st) red[threadIdx.x] += red[threadIdx.x + st];
        __syncthreads();
    }
    if (threadIdx.x == 0)
        out[NQE] = red[0] / (float)((size_t)N_ * C_);
}

// ---------------------------------------------------------------------------
extern "C" void kernel_launch(void* const* d_in, const int* in_sizes, int n_in,
                              void* d_out, int out_size) {
    const float* x  = (const float*)d_in[0];   // [16,256,32,32]
    const float* cb = (const float*)d_in[1];   // [8192,256]
    float* out = (float*)d_out;                // [qe | loss | indices]

    cudaFuncSetAttribute(argmin_mma_kernel,
                         cudaFuncAttributeMaxDynamicSharedMemorySize,
                         SMEM_BYTES);

    cnorm_kernel<<<K_ / 8, 256>>>(cb);
    dim3 grid(N_ / TM, K_ / TN);
    argmin_mma_kernel<<<grid, 256, SMEM_BYTES>>>(x, cb);
    rerank_kernel<<<N_ / 8, 256>>>(x, cb);
    gather_kernel<<<B_ * C_, 256>>>(x, cb, out);
    loss_kernel<<<1, 256>>>(out);
}

// round 9
// speedup vs baseline: 1.3862x; 1.3862x over previous
#include <cuda_runtime.h>
#include <cuda_bf16.h>
#include <cstdint>

// Problem constants
#define B_   16
#define C_   256
#define HW_  1024
#define K_   8192
#define N_   16384            // tokens
#define NQE  4194304          // qe elems

// Tiling
#define TM 128                 // tokens per CTA
#define TN 128                 // codes per CTA
#define KCH 32                 // K chunk (floats) = 16 k-pairs
#define NCHUNK (C_ / KCH)      // 8
#define NCAND 256              // candidates per token (64 ctaY * 2 nwarps * 2)
#define MARGIN 1.0f            // exact-rerank margin (covers 1-term bf16 noise)

// smem (uint32 units). A: [kp][t] hi-only, stride 136 (tg*8+g -> 32 distinct banks)
// B: [nr][kp] hi-only, stride 20 (g*20 mod 32 spans 8 banks, +tg -> 32 distinct)
#define AST_A 136
#define A_U32 (16 * AST_A)             // 2176
#define BSTW 20
#define B_U32 (128 * BSTW)              // 2560
#define STAGE_U32 (A_U32 + B_U32)       // 4736
#define SMEM_BYTES (2 * STAGE_U32 * 4)  // 37888

// Scratch
__device__ unsigned long long g_cand[(size_t)N_ * NCAND];   // 32MB
__device__ unsigned int g_idx[N_];
__device__ float g_cnorm[K_];
__device__ float g_partial[B_ * C_];

__device__ __forceinline__ unsigned int fkey(float f) {
    unsigned int b = __float_as_uint(f);
    return (b & 0x80000000u) ? ~b : (b | 0x80000000u);
}
__device__ __forceinline__ float unfkey(unsigned int k) {
    unsigned int b = (k & 0x80000000u) ? (k & 0x7FFFFFFFu) : ~k;
    return __uint_as_float(b);
}
__device__ __forceinline__ uint32_t hi_pair(float v0, float v1) {
    __nv_bfloat162 hp = __floats2bfloat162_rn(v0, v1);
    return *(uint32_t*)&hp;
}

#define MMA_BF16(D, A, B0, B1)                                              \
    asm volatile("mma.sync.aligned.m16n8k16.row.col.f32.bf16.bf16.f32 "     \
        "{%0,%1,%2,%3},{%4,%5,%6,%7},{%8,%9},{%0,%1,%2,%3};"                \
        : "+f"((D)[0]), "+f"((D)[1]), "+f"((D)[2]), "+f"((D)[3])            \
        : "r"((A)[0]), "r"((A)[1]), "r"((A)[2]), "r"((A)[3]),               \
          "r"(B0), "r"(B1))

// ---------------------------------------------------------------------------
// Kernel 1: codebook squared norms
__global__ void cnorm_kernel(const float* __restrict__ cb) {
    int code = blockIdx.x * 8 + (threadIdx.x >> 5);
    int lane = threadIdx.x & 31;
    const float4* row = (const float4*)(cb + (size_t)code * C_);
    float s = 0.0f;
#pragma unroll
    for (int r = 0; r < 2; r++) {
        float4 v = row[lane + 32 * r];
        s += v.x * v.x + v.y * v.y + v.z * v.z + v.w * v.w;
    }
#pragma unroll
    for (int off = 16; off; off >>= 1)
        s += __shfl_xor_sync(0xFFFFFFFFu, s, off);
    if (lane == 0) g_cnorm[code] = s;
}

// ---------------------------------------------------------------------------
// Kernel 2: pure bf16 screening GEMM (1-term), top-2 candidates per n-warp
// per token, race-free writes. grid=(128,64), block=256 (4m x 2n warps).
__global__ void __launch_bounds__(256, 2)
argmin_mma_kernel(const float* __restrict__ x, const float* __restrict__ cb) {
    extern __shared__ uint32_t smemu[];
    __shared__ float cnS[TN];

    const int tid = threadIdx.x;
    const int wid = tid >> 5;
    const int lane = tid & 31;
    const int g  = lane >> 2;
    const int tg = lane & 3;
    const int m0w = (wid & 3) * 32;
    const int n0w = (wid >> 2) * 64;

    const int n0tok = blockIdx.x * TM;
    const int b   = n0tok >> 10;
    const int hw0 = n0tok & 1023;
    const int j0  = blockIdx.y * TN;

    if (tid < TN) cnS[tid] = g_cnorm[j0 + tid];

    const float* ga = x + (size_t)b * C_ * HW_ + hw0;   // [c][t] stride HW_
    const float* gb = cb + (size_t)j0 * C_;             // [n][c] row-major

    float d[2][8][4];
#pragma unroll
    for (int i = 0; i < 2; i++)
#pragma unroll
        for (int j = 0; j < 8; j++)
#pragma unroll
            for (int e = 0; e < 4; e++) d[i][j][e] = 0.0f;

    float2 va2[8];
    float4 vb[4];

    auto gld = [&](int k) {
        const int c0 = k * KCH;
#pragma unroll
        for (int r = 0; r < 8; r++) {
            int idx = tid + r * 256;
            int t = idx & 127, kp = idx >> 7;
            va2[r].x = ga[(size_t)(c0 + 2 * kp) * HW_ + t];
            va2[r].y = ga[(size_t)(c0 + 2 * kp + 1) * HW_ + t];
        }
#pragma unroll
        for (int s = 0; s < 4; s++) {
            int f4 = tid + s * 256;
            int rowB = f4 >> 3, q = f4 & 7;
            vb[s] = *(const float4*)(gb + (size_t)rowB * C_ + c0 + q * 4);
        }
    };

    auto sts = [&](int stg) {
        uint32_t* As = smemu + stg * STAGE_U32;
        uint32_t* Bs = As + A_U32;
#pragma unroll
        for (int r = 0; r < 8; r++) {
            int idx = tid + r * 256;
            int t = idx & 127, kp = idx >> 7;
            As[kp * AST_A + t] = hi_pair(va2[r].x, va2[r].y);
        }
#pragma unroll
        for (int s = 0; s < 4; s++) {
            int f4 = tid + s * 256;
            int rowB = f4 >> 3, q = f4 & 7;
            Bs[rowB * BSTW + 2 * q]     = hi_pair(vb[s].x, vb[s].y);
            Bs[rowB * BSTW + 2 * q + 1] = hi_pair(vb[s].z, vb[s].w);
        }
    };

    auto mma_stage = [&](int stg) {
        const uint32_t* As = smemu + stg * STAGE_U32;
        const uint32_t* Bs = As + A_U32;
#pragma unroll
        for (int kk = 0; kk < 2; kk++) {
            const int kb = kk * 8 + tg;
            uint32_t ah[2][4];
#pragma unroll
            for (int dm = 0; dm < 2; dm++) {
                int mc = m0w + 16 * dm + g;
                ah[dm][0] = As[kb * AST_A + mc];
                ah[dm][1] = As[kb * AST_A + mc + 8];
                ah[dm][2] = As[(kb + 4) * AST_A + mc];
                ah[dm][3] = As[(kb + 4) * AST_A + mc + 8];
            }
#pragma unroll
            for (int dn = 0; dn < 8; dn++) {
                int nr = n0w + 8 * dn + g;
                uint32_t b0 = Bs[nr * BSTW + kb];
                uint32_t b1 = Bs[nr * BSTW + kb + 4];
                MMA_BF16(d[0][dn], ah[0], b0, b1);
                MMA_BF16(d[1][dn], ah[1], b0, b1);
            }
        }
    };

    gld(0);
    sts(0);
    __syncthreads();
#pragma unroll 1
    for (int k = 0; k < NCHUNK; k++) {
        if (k + 1 < NCHUNK) gld(k + 1);
        mma_stage(k & 1);
        if (k + 1 < NCHUNK) sts((k + 1) & 1);
        __syncthreads();
    }

    // epilogue: per n-warp top-2 per token row, race-free candidate writes
#pragma unroll
    for (int dm = 0; dm < 2; dm++) {
#pragma unroll
        for (int h = 0; h < 2; h++) {
            unsigned long long p1 = 0xFFFFFFFFFFFFFFFFull;
            unsigned long long p2 = 0xFFFFFFFFFFFFFFFFull;
#pragma unroll
            for (int dn = 0; dn < 8; dn++) {
#pragma unroll
                for (int e = 0; e < 2; e++) {
                    int col = n0w + 8 * dn + 2 * tg + e;
                    float sc = fmaf(-2.0f, d[dm][dn][2 * h + e], cnS[col]);
                    unsigned long long p =
                        ((unsigned long long)fkey(sc) << 32) |
                        (unsigned int)(j0 + col);
                    if (p < p1) { p2 = p1; p1 = p; }
                    else if (p < p2) { p2 = p; }
                }
            }
#pragma unroll
            for (int off = 1; off <= 2; off <<= 1) {
                unsigned long long q1 = __shfl_xor_sync(0xFFFFFFFFu, p1, off);
                unsigned long long q2 = __shfl_xor_sync(0xFFFFFFFFu, p2, off);
                if (q1 < p1) { p2 = (p1 < q2) ? p1 : q2; p1 = q1; }
                else         { p2 = (p2 < q1) ? p2 : q1; }
            }
            if (tg == 0) {
                int tok = n0tok + m0w + 16 * dm + 8 * h + g;
                size_t base = (size_t)tok * NCAND + blockIdx.y * 4 + (wid >> 2) * 2;
                g_cand[base] = p1;
                g_cand[base + 1] = p2;
            }
        }
    }
}

// ---------------------------------------------------------------------------
// Kernel 3: exact fp32 rerank. One warp per token over 256 candidates.
__global__ void __launch_bounds__(256)
rerank_kernel(const float* __restrict__ x, const float* __restrict__ cb) {
    const int wid = threadIdx.x >> 5;
    const int lane = threadIdx.x & 31;
    const int tok = blockIdx.x * 8 + wid;
    const unsigned long long* cand = g_cand + (size_t)tok * NCAND;

    unsigned long long v[8];
    unsigned long long mn = 0xFFFFFFFFFFFFFFFFull;
#pragma unroll
    for (int r = 0; r < 8; r++) {
        v[r] = cand[lane + 32 * r];
        if (v[r] < mn) mn = v[r];
    }
#pragma unroll
    for (int off = 16; off; off >>= 1) {
        unsigned long long o = __shfl_xor_sync(0xFFFFFFFFu, mn, off);
        if (o < mn) mn = o;
    }
    const float thr = unfkey((unsigned int)(mn >> 32)) + MARGIN;

    const int b = tok >> 10, hw = tok & 1023;
    const float* xt = x + (size_t)b * C_ * HW_ + hw;
    float xr[8];
#pragma unroll
    for (int q = 0; q < 8; q++)
        xr[q] = xt[(size_t)(lane + 32 * q) * HW_];

    float best_s = __uint_as_float(0x7F800000u);   // +inf
    unsigned int best_j = 0xFFFFFFFFu;
#pragma unroll 1
    for (int r = 0; r < 8; r++) {
        float sf = unfkey((unsigned int)(v[r] >> 32));
        unsigned int m = __ballot_sync(0xFFFFFFFFu, sf <= thr);
        while (m) {
            int src = __ffs(m) - 1;
            m &= m - 1;
            unsigned long long c = __shfl_sync(0xFFFFFFFFu, v[r], src);
            unsigned int j = (unsigned int)c;
            const float* row = cb + (size_t)j * C_;
            float dot = 0.0f;
#pragma unroll
            for (int q = 0; q < 8; q++)
                dot = fmaf(xr[q], row[lane + 32 * q], dot);
#pragma unroll
            for (int off = 16; off; off >>= 1)
                dot += __shfl_xor_sync(0xFFFFFFFFu, dot, off);
            float sc = fmaf(-2.0f, dot, g_cnorm[j]);
            if (sc < best_s || (sc == best_s && j < best_j)) {
                best_s = sc;
                best_j = j;
            }
        }
    }
    if (lane == 0) g_idx[tok] = best_j;
}

// ---------------------------------------------------------------------------
// Kernel 4: gather q, write qe + indices, per-block loss partials
__global__ void gather_kernel(const float* __restrict__ x,
                              const float* __restrict__ cb,
                              float* __restrict__ out) {
    const int bc = blockIdx.x;
    const int b = bc >> 8, c = bc & 255;
    const float* xrow = x + (size_t)bc * HW_;
    float* orow = out + (size_t)bc * HW_;
    float lsum = 0.0f;
#pragma unroll
    for (int r = 0; r < 4; r++) {
        int hw = threadIdx.x + r * 256;
        int n = b * HW_ + hw;
        unsigned int idx = g_idx[n];
        float q = cb[(size_t)idx * C_ + c];
        float dd = xrow[hw] - q;
        lsum += dd * dd;
        orow[hw] = q;
        if (c == 0) out[NQE + 1 + n] = (float)idx;
    }
    __shared__ float red[256];
    red[threadIdx.x] = lsum;
    __syncthreads();
#pragma unroll
    for (int s = 128; s; s >>= 1) {
        if (threadIdx.x < s) red[threadIdx.x] += red[threadIdx.x + s];
        __syncthreads();
    }
    if (threadIdx.x == 0) g_partial[bc] = red[0];
}

// Kernel 5: deterministic final loss reduction
__global__ void loss_kernel(float* __restrict__ out) {
    __shared__ float red[256];
    float s = 0.0f;
    for (int i = threadIdx.x; i < B_ * C_; i += 256) s += g_partial[i];
    red[threadIdx.x] = s;
    __syncthreads();
#pragma unroll
    for (int st = 128; st; st >>= 1) {
        if (threadIdx.x < st) red[threadIdx.x] += red[threadIdx.x + st];
        __syncthreads();
    }
    if (threadIdx.x == 0)
        out[NQE] = red[0] / (float)((size_t)N_ * C_);
}

// ---------------------------------------------------------------------------
extern "C" void kernel_launch(void* const* d_in, const int* in_sizes, int n_in,
                              void* d_out, int out_size) {
    const float* x  = (const float*)d_in[0];   // [16,256,32,32]
    const float* cb = (const float*)d_in[1];   // [8192,256]
    float* out = (float*)d_out;                // [qe | loss | indices]

    cudaFuncSetAttribute(argmin_mma_kernel,
                         cudaFuncAttributeMaxDynamicSharedMemorySize,
                         SMEM_BYTES);

    cnorm_kernel<<<K_ / 8, 256>>>(cb);
    dim3 grid(N_ / TM, K_ / TN);
    argmin_mma_kernel<<<grid, 256, SMEM_BYTES>>>(x, cb);
    rerank_kernel<<<N_ / 8, 256>>>(x, cb);
    gather_kernel<<<B_ * C_, 256>>>(x, cb, out);
    loss_kernel<<<1, 256>>>(out);
}

// round 10
// speedup vs baseline: 1.7150x; 1.2373x over previous
#include <cuda_runtime.h>
#include <cuda_bf16.h>
#include <cstdint>

// Problem constants
#define B_   16
#define C_   256
#define HW_  1024
#define K_   8192
#define N_   16384            // tokens
#define NQE  4194304          // qe elems

// Tiling
#define TM 128                 // tokens per CTA
#define TN 128                 // codes per CTA
#define KCH 32                 // K chunk (floats) = 16 k-pairs
#define NCHUNK (C_ / KCH)      // 8
#define NCAND 256              // candidates per token (64 ctaY * 2 nwarps * 2)
#define MARGIN 1.0f            // exact-rerank margin (covers 1-term bf16 noise)

// smem (uint32 units). A: [kp][t] stride 136; B: [nr][kp] stride 20.
#define AST_A 136
#define A_U32 (16 * AST_A)             // 2176
#define BSTW 20
#define B_U32 (128 * BSTW)              // 2560
#define STAGE_U32 (A_U32 + B_U32)       // 4736
#define SMEM_BYTES (2 * STAGE_U32 * 4)  // 37888

// Scratch
__device__ unsigned long long g_cand[(size_t)N_ * NCAND];   // 32MB
__device__ uint32_t g_xp[(size_t)B_ * 128 * HW_];           // 8MB  bf16-pair x
__device__ uint32_t g_cbp[(size_t)K_ * 128];                // 4MB  bf16-pair cb
__device__ unsigned int g_idx[N_];
__device__ float g_cnorm[K_];
__device__ float g_partial[B_ * C_];

__device__ __forceinline__ unsigned int fkey(float f) {
    unsigned int b = __float_as_uint(f);
    return (b & 0x80000000u) ? ~b : (b | 0x80000000u);
}
__device__ __forceinline__ float unfkey(unsigned int k) {
    unsigned int b = (k & 0x80000000u) ? (k & 0x7FFFFFFFu) : ~k;
    return __uint_as_float(b);
}
__device__ __forceinline__ uint32_t hi_pair(float v0, float v1) {
    __nv_bfloat162 hp = __floats2bfloat162_rn(v0, v1);
    return *(uint32_t*)&hp;
}
__device__ __forceinline__ uint32_t smem_u32(const void* p) {
    uint32_t a;
    asm("{ .reg .u64 t; cvta.to.shared.u64 t, %1; cvt.u32.u64 %0, t; }"
        : "=r"(a) : "l"(p));
    return a;
}
__device__ __forceinline__ void cp16(uint32_t dst, const void* src) {
    asm volatile("cp.async.cg.shared.global [%0], [%1], 16;"
                 :: "r"(dst), "l"(src));
}

#define MMA_BF16(D, A, B0, B1)                                              \
    asm volatile("mma.sync.aligned.m16n8k16.row.col.f32.bf16.bf16.f32 "     \
        "{%0,%1,%2,%3},{%4,%5,%6,%7},{%8,%9},{%0,%1,%2,%3};"                \
        : "+f"((D)[0]), "+f"((D)[1]), "+f"((D)[2]), "+f"((D)[3])            \
        : "r"((A)[0]), "r"((A)[1]), "r"((A)[2]), "r"((A)[3]),               \
          "r"(B0), "r"(B1))

// ---------------------------------------------------------------------------
// Kernel 0a: preconvert x -> bf16 pairs, layout [b][kp][t]
__global__ void pconv_x_kernel(const float* __restrict__ x) {
    const int blk = blockIdx.x;              // b*128 + kp
    const int b = blk >> 7, kp = blk & 127;
    const float4* r0 = (const float4*)(x + ((size_t)(b * C_ + 2 * kp)) * HW_);
    const float4* r1 = (const float4*)(x + ((size_t)(b * C_ + 2 * kp + 1)) * HW_);
    const int t4 = threadIdx.x;              // 256 threads x 4 tokens
    float4 a = r0[t4], c = r1[t4];
    uint4 o;
    o.x = hi_pair(a.x, c.x);
    o.y = hi_pair(a.y, c.y);
    o.z = hi_pair(a.z, c.z);
    o.w = hi_pair(a.w, c.w);
    ((uint4*)(g_xp + (size_t)blk * HW_))[t4] = o;
}

// Kernel 0b: preconvert codebook -> bf16 pairs [n][kp], fused with cnorm.
__global__ void pconv_cb_kernel(const float* __restrict__ cb) {
    int code = blockIdx.x * 8 + (threadIdx.x >> 5);
    int lane = threadIdx.x & 31;
    const float4* row = (const float4*)(cb + (size_t)code * C_);
    uint2* orow = (uint2*)(g_cbp + (size_t)code * 128);
    float s = 0.0f;
#pragma unroll
    for (int r = 0; r < 2; r++) {
        float4 v = row[lane + 32 * r];
        s += v.x * v.x + v.y * v.y + v.z * v.z + v.w * v.w;
        uint2 p;
        p.x = hi_pair(v.x, v.y);
        p.y = hi_pair(v.z, v.w);
        orow[lane + 32 * r] = p;
    }
#pragma unroll
    for (int off = 16; off; off >>= 1)
        s += __shfl_xor_sync(0xFFFFFFFFu, s, off);
    if (lane == 0) g_cnorm[code] = s;
}

// ---------------------------------------------------------------------------
// Kernel 2: pure bf16 screening GEMM, cp.async tile loads, top-2 per n-warp
// per token. grid=(128,64), block=256 (4m x 2n warps).
__global__ void __launch_bounds__(256, 2)
argmin_mma_kernel() {
    extern __shared__ uint32_t smemu[];
    __shared__ float cnS[TN];

    const int tid = threadIdx.x;
    const int wid = tid >> 5;
    const int lane = tid & 31;
    const int g  = lane >> 2;
    const int tg = lane & 3;
    const int m0w = (wid & 3) * 32;
    const int n0w = (wid >> 2) * 64;

    const int n0tok = blockIdx.x * TM;
    const int b   = n0tok >> 10;
    const int hw0 = n0tok & 1023;
    const int j0  = blockIdx.y * TN;

    if (tid < TN) cnS[tid] = g_cnorm[j0 + tid];

    const uint32_t sbase = smem_u32(smemu);
    const uint32_t* xpB = g_xp + (size_t)b * (128 * HW_) + hw0;  // + kp*HW_ + t

    float d[2][8][4];
#pragma unroll
    for (int i = 0; i < 2; i++)
#pragma unroll
        for (int j = 0; j < 8; j++)
#pragma unroll
            for (int e = 0; e < 4; e++) d[i][j][e] = 0.0f;

    auto fill = [&](int k, int stg) {
        uint32_t As = sbase + (uint32_t)(stg * STAGE_U32 * 4);
        uint32_t Bs = As + A_U32 * 4;
        // A tile: 16 kp-rows x 128 tokens (512B/row) = 512 x 16B granules
#pragma unroll
        for (int r = 0; r < 2; r++) {
            int gi = tid + r * 256;
            int row = gi >> 5, c16 = gi & 31;
            cp16(As + (uint32_t)(row * (AST_A * 4) + c16 * 16),
                 xpB + (size_t)(k * 16 + row) * HW_ + c16 * 4);
        }
        // B tile: 128 n-rows x 16 kp (64B/row) = 512 x 16B granules
#pragma unroll
        for (int r = 0; r < 2; r++) {
            int gi = tid + r * 256;
            int nr = gi >> 2, c4 = gi & 3;
            cp16(Bs + (uint32_t)(nr * (BSTW * 4) + c4 * 16),
                 g_cbp + (size_t)(j0 + nr) * 128 + k * 16 + c4 * 4);
        }
        asm volatile("cp.async.commit_group;" ::: "memory");
    };

    auto mma_stage = [&](int stg) {
        const uint32_t* As = smemu + stg * STAGE_U32;
        const uint32_t* Bs = As + A_U32;
#pragma unroll
        for (int kk = 0; kk < 2; kk++) {
            const int kb = kk * 8 + tg;
            uint32_t ah[2][4];
#pragma unroll
            for (int dm = 0; dm < 2; dm++) {
                int mc = m0w + 16 * dm + g;
                ah[dm][0] = As[kb * AST_A + mc];
                ah[dm][1] = As[kb * AST_A + mc + 8];
                ah[dm][2] = As[(kb + 4) * AST_A + mc];
                ah[dm][3] = As[(kb + 4) * AST_A + mc + 8];
            }
#pragma unroll
            for (int dn = 0; dn < 8; dn++) {
                int nr = n0w + 8 * dn + g;
                uint32_t b0 = Bs[nr * BSTW + kb];
                uint32_t b1 = Bs[nr * BSTW + kb + 4];
                MMA_BF16(d[0][dn], ah[0], b0, b1);
                MMA_BF16(d[1][dn], ah[1], b0, b1);
            }
        }
    };

    fill(0, 0);
    fill(1, 1);
#pragma unroll 1
    for (int k = 0; k < NCHUNK; k++) {
        asm volatile("cp.async.wait_group 1;" ::: "memory");
        __syncthreads();
        mma_stage(k & 1);
        __syncthreads();
        if (k + 2 < NCHUNK) fill(k + 2, k & 1);
        else asm volatile("cp.async.commit_group;" ::: "memory");
    }

    // epilogue: per n-warp top-2 per token row, race-free candidate writes
#pragma unroll
    for (int dm = 0; dm < 2; dm++) {
#pragma unroll
        for (int h = 0; h < 2; h++) {
            unsigned long long p1 = 0xFFFFFFFFFFFFFFFFull;
            unsigned long long p2 = 0xFFFFFFFFFFFFFFFFull;
#pragma unroll
            for (int dn = 0; dn < 8; dn++) {
#pragma unroll
                for (int e = 0; e < 2; e++) {
                    int col = n0w + 8 * dn + 2 * tg + e;
                    float sc = fmaf(-2.0f, d[dm][dn][2 * h + e], cnS[col]);
                    unsigned long long p =
                        ((unsigned long long)fkey(sc) << 32) |
                        (unsigned int)(j0 + col);
                    if (p < p1) { p2 = p1; p1 = p; }
                    else if (p < p2) { p2 = p; }
                }
            }
#pragma unroll
            for (int off = 1; off <= 2; off <<= 1) {
                unsigned long long q1 = __shfl_xor_sync(0xFFFFFFFFu, p1, off);
                unsigned long long q2 = __shfl_xor_sync(0xFFFFFFFFu, p2, off);
                if (q1 < p1) { p2 = (p1 < q2) ? p1 : q2; p1 = q1; }
                else         { p2 = (p2 < q1) ? p2 : q1; }
            }
            if (tg == 0) {
                int tok = n0tok + m0w + 16 * dm + 8 * h + g;
                size_t base = (size_t)tok * NCAND + blockIdx.y * 4 + (wid >> 2) * 2;
                g_cand[base] = p1;
                g_cand[base + 1] = p2;
            }
        }
    }
}

// ---------------------------------------------------------------------------
// Kernel 3: exact fp32 rerank. One warp per token over 256 candidates.
__global__ void __launch_bounds__(256)
rerank_kernel(const float* __restrict__ x, const float* __restrict__ cb) {
    const int wid = threadIdx.x >> 5;
    const int lane = threadIdx.x & 31;
    const int tok = blockIdx.x * 8 + wid;
    const unsigned long long* cand = g_cand + (size_t)tok * NCAND;

    unsigned long long v[8];
    unsigned long long mn = 0xFFFFFFFFFFFFFFFFull;
#pragma unroll
    for (int r = 0; r < 8; r++) {
        v[r] = cand[lane + 32 * r];
        if (v[r] < mn) mn = v[r];
    }
#pragma unroll
    for (int off = 16; off; off >>= 1) {
        unsigned long long o = __shfl_xor_sync(0xFFFFFFFFu, mn, off);
        if (o < mn) mn = o;
    }
    const float thr = unfkey((unsigned int)(mn >> 32)) + MARGIN;

    const int b = tok >> 10, hw = tok & 1023;
    const float* xt = x + (size_t)b * C_ * HW_ + hw;
    float xr[8];
#pragma unroll
    for (int q = 0; q < 8; q++)
        xr[q] = xt[(size_t)(lane + 32 * q) * HW_];

    float best_s = __uint_as_float(0x7F800000u);   // +inf
    unsigned int best_j = 0xFFFFFFFFu;
#pragma unroll 1
    for (int r = 0; r < 8; r++) {
        float sf = unfkey((unsigned int)(v[r] >> 32));
        unsigned int m = __ballot_sync(0xFFFFFFFFu, sf <= thr);
        while (m) {
            int src = __ffs(m) - 1;
            m &= m - 1;
            unsigned long long c = __shfl_sync(0xFFFFFFFFu, v[r], src);
            unsigned int j = (unsigned int)c;
            const float* row = cb + (size_t)j * C_;
            float dot = 0.0f;
#pragma unroll
            for (int q = 0; q < 8; q++)
                dot = fmaf(xr[q], row[lane + 32 * q], dot);
#pragma unroll
            for (int off = 16; off; off >>= 1)
                dot += __shfl_xor_sync(0xFFFFFFFFu, dot, off);
            float sc = fmaf(-2.0f, dot, g_cnorm[j]);
            if (sc < best_s || (sc == best_s && j < best_j)) {
                best_s = sc;
                best_j = j;
            }
        }
    }
    if (lane == 0) g_idx[tok] = best_j;
}

// ---------------------------------------------------------------------------
// Kernel 4: gather q, write qe + indices, per-block loss partials
__global__ void gather_kernel(const float* __restrict__ x,
                              const float* __restrict__ cb,
                              float* __restrict__ out) {
    const int bc = blockIdx.x;
    const int b = bc >> 8, c = bc & 255;
    const float* xrow = x + (size_t)bc * HW_;
    float* orow = out + (size_t)bc * HW_;
    float lsum = 0.0f;
#pragma unroll
    for (int r = 0; r < 4; r++) {
        int hw = threadIdx.x + r * 256;
        int n = b * HW_ + hw;
        unsigned int idx = g_idx[n];
        float q = cb[(size_t)idx * C_ + c];
        float dd = xrow[hw] - q;
        lsum += dd * dd;
        orow[hw] = q;
        if (c == 0) out[NQE + 1 + n] = (float)idx;
    }
    __shared__ float red[256];
    red[threadIdx.x] = lsum;
    __syncthreads();
#pragma unroll
    for (int s = 128; s; s >>= 1) {
        if (threadIdx.x < s) red[threadIdx.x] += red[threadIdx.x + s];
        __syncthreads();
    }
    if (threadIdx.x == 0) g_partial[bc] = red[0];
}

// Kernel 5: deterministic final loss reduction
__global__ void loss_kernel(float* __restrict__ out) {
    __shared__ float red[256];
    float s = 0.0f;
    for (int i = threadIdx.x; i < B_ * C_; i += 256) s += g_partial[i];
    red[threadIdx.x] = s;
    __syncthreads();
#pragma unroll
    for (int st = 128; st; st >>= 1) {
        if (threadIdx.x < st) red[threadIdx.x] += red[threadIdx.x + st];
        __syncthreads();
    }
    if (threadIdx.x == 0)
        out[NQE] = red[0] / (float)((size_t)N_ * C_);
}

// ---------------------------------------------------------------------------
extern "C" void kernel_launch(void* const* d_in, const int* in_sizes, int n_in,
                              void* d_out, int out_size) {
    const float* x  = (const float*)d_in[0];   // [16,256,32,32]
    const float* cb = (const float*)d_in[1];   // [8192,256]
    float* out = (float*)d_out;                // [qe | loss | indices]

    cudaFuncSetAttribute(argmin_mma_kernel,
                         cudaFuncAttributeMaxDynamicSharedMemorySize,
                         SMEM_BYTES);

    pconv_x_kernel<<<B_ * 128, 256>>>(x);
    pconv_cb_kernel<<<K_ / 8, 256>>>(cb);
    dim3 grid(N_ / TM, K_ / TN);
    argmin_mma_kernel<<<grid, 256, SMEM_BYTES>>>();
    rerank_kernel<<<N_ / 8, 256>>>(x, cb);
    gather_kernel<<<B_ * C_, 256>>>(x, cb, out);
    loss_kernel<<<1, 256>>>(out);
}